// round 14
// baseline (speedup 1.0000x reference)
#include <cuda_runtime.h>
#include <cuda_bf16.h>
#include <cstdint>
#include <math.h>

#define Bc 4
#define Tc 2048
#define Cc 768
#define Hc 6
#define Dc 128
#define Mrows (Bc*Tc)

// bf16 split scratch
__device__ __align__(16) __nv_bfloat16 g_xhi[Mrows*Cc];
__device__ __align__(16) __nv_bfloat16 g_xlo[Mrows*Cc];
__device__ __align__(16) __nv_bfloat16 g_whi[4*Cc*Cc];
__device__ __align__(16) __nv_bfloat16 g_wlo[4*Cc*Cc];
__device__ __align__(16) __nv_bfloat16 g_qhi[Mrows*Cc];
__device__ __align__(16) __nv_bfloat16 g_qlo[Mrows*Cc];
__device__ __align__(16) __nv_bfloat16 g_khi[Mrows*Cc];
__device__ __align__(16) __nv_bfloat16 g_klo[Mrows*Cc];
__device__ __align__(16) __nv_bfloat16 g_vhi[Mrows*Cc];
__device__ __align__(16) __nv_bfloat16 g_vlo[Mrows*Cc];
__device__ __align__(16) __nv_bfloat16 g_ohi[Mrows*Cc];
__device__ __align__(16) __nv_bfloat16 g_olo[Mrows*Cc];

// ---------------------------------------------------------------------------
// helpers
// ---------------------------------------------------------------------------
__device__ __forceinline__ void mma16816(float* c, const uint32_t* a,
                                         uint32_t b0, uint32_t b1) {
    asm volatile(
        "mma.sync.aligned.m16n8k16.row.col.f32.bf16.bf16.f32 "
        "{%0,%1,%2,%3}, {%4,%5,%6,%7}, {%8,%9}, {%0,%1,%2,%3};\n"
        : "+f"(c[0]), "+f"(c[1]), "+f"(c[2]), "+f"(c[3])
        : "r"(a[0]), "r"(a[1]), "r"(a[2]), "r"(a[3]), "r"(b0), "r"(b1));
}

__device__ __forceinline__ uint32_t pack_bf16x2_rn(float f0, float f1) {
    uint32_t r;
    asm("cvt.rn.bf16x2.f32 %0, %1, %2;\n" : "=r"(r) : "f"(f1), "f"(f0));
    return r;
}

__device__ __forceinline__ uint32_t cvta_s(const void* p) {
    return (uint32_t)__cvta_generic_to_shared(p);
}

__device__ __forceinline__ void ldsm4(uint32_t* r, uint32_t a) {
    asm volatile("ldmatrix.sync.aligned.m8n8.x4.shared.b16 {%0,%1,%2,%3}, [%4];"
        : "=r"(r[0]), "=r"(r[1]), "=r"(r[2]), "=r"(r[3]) : "r"(a));
}

__device__ __forceinline__ void ldsm4t(uint32_t* r, uint32_t a) {
    asm volatile("ldmatrix.sync.aligned.m8n8.x4.trans.shared.b16 {%0,%1,%2,%3}, [%4];"
        : "=r"(r[0]), "=r"(r[1]), "=r"(r[2]), "=r"(r[3]) : "r"(a));
}

__device__ __forceinline__ float ex2(float x) {
    float y;
    asm("ex2.approx.ftz.f32 %0, %1;" : "=f"(y) : "f"(x));
    return y;
}

__device__ __forceinline__ void cp16(uint32_t dst, const void* src) {
    asm volatile("cp.async.cg.shared.global [%0], [%1], 16;\n"
                 :: "r"(dst), "l"(src) : "memory");
}

__device__ __forceinline__ void split_pair(
    float f0, float f1, uint32_t& hp, uint32_t& lp)
{
    uint32_t h0 = __float_as_uint(f0) & 0xFFFF0000u;
    uint32_t h1 = __float_as_uint(f1) & 0xFFFF0000u;
    hp = (h0 >> 16) | h1;
    lp = pack_bf16x2_rn(f0 - __uint_as_float(h0), f1 - __uint_as_float(h1));
}

__device__ __forceinline__ void split4(
    __nv_bfloat16* hi, __nv_bfloat16* lo, int idx, float4 v)
{
    float f[4] = {v.x, v.y, v.z, v.w};
    #pragma unroll
    for (int p = 0; p < 2; p++) {
        uint32_t hp, lp;
        split_pair(f[2*p], f[2*p+1], hp, lp);
        *reinterpret_cast<uint32_t*>(hi + idx + 2*p) = hp;
        *reinterpret_cast<uint32_t*>(lo + idx + 2*p) = lp;
    }
}

// ---------------------------------------------------------------------------
// split passes
// ---------------------------------------------------------------------------
__global__ __launch_bounds__(256) void split_f32(
    const float* __restrict__ src, __nv_bfloat16* __restrict__ hi,
    __nv_bfloat16* __restrict__ lo, int n)
{
    int i = (blockIdx.x*256 + threadIdx.x)*4;
    if (i < n)
        split4(hi, lo, i, *reinterpret_cast<const float4*>(src + i));
}

__global__ __launch_bounds__(256) void split_w4(
    const float* __restrict__ w0, const float* __restrict__ w1,
    const float* __restrict__ w2, const float* __restrict__ w3,
    __nv_bfloat16* __restrict__ hi, __nv_bfloat16* __restrict__ lo)
{
    const int z = blockIdx.y;
    const float* src = (z == 0) ? w0 : (z == 1) ? w1 : (z == 2) ? w2 : w3;
    const int nw = Cc*Cc;
    int i = (blockIdx.x*256 + threadIdx.x)*4;
    if (i < nw)
        split4(hi + (size_t)z*nw, lo + (size_t)z*nw, i,
               *reinterpret_cast<const float4*>(src + i));
}

// ---------------------------------------------------------------------------
// pipelined bf16 3-pass GEMM core (NT)
// ---------------------------------------------------------------------------
#define SAB 40
#define STAGE_B 40960
#define GSM_BYTES (3*STAGE_B)
#define FTS 132          // fp32 smem tile row stride for fused rope epilogue

struct GemmCore {
    float acc[2][8][4];
    int wm, wn, g, tg;

    __device__ __forceinline__ void run(
        const __nv_bfloat16* Ahi, const __nv_bfloat16* Alo,
        const __nv_bfloat16* Bhi, const __nv_bfloat16* Blo,
        int bm, int bn, int K, uint32_t sm0)
    {
        const int tid  = threadIdx.x;
        const int warp = tid >> 5, lane = tid & 31;
        wm = warp >> 1; wn = warp & 1;
        g  = lane >> 2; tg = lane & 3;

        const int lrow = tid >> 1;
        const int lk   = (tid & 1) * 16;

        const __nv_bfloat16* pAh = Ahi + (size_t)(bm + lrow)*K + lk;
        const __nv_bfloat16* pAl = Alo + (size_t)(bm + lrow)*K + lk;
        const __nv_bfloat16* pBh = Bhi + (size_t)(bn + lrow)*K + lk;
        const __nv_bfloat16* pBl = Blo + (size_t)(bn + lrow)*K + lk;
        const uint32_t dbase = sm0 + (uint32_t)(lrow*SAB + lk)*2;

        const int nk = K / 32;

        auto issue = [&](int kc) {
            if (kc < nk) {
                const int ko = kc*32;
                const uint32_t d = dbase + (uint32_t)(kc%3)*STAGE_B;
                cp16(d,             pAh + ko);  cp16(d + 16,         pAh + ko + 8);
                cp16(d + 10240,     pAl + ko);  cp16(d + 10240 + 16, pAl + ko + 8);
                cp16(d + 20480,     pBh + ko);  cp16(d + 20480 + 16, pBh + ko + 8);
                cp16(d + 30720,     pBl + ko);  cp16(d + 30720 + 16, pBl + ko + 8);
            }
            asm volatile("cp.async.commit_group;\n" ::: "memory");
        };

        #pragma unroll
        for (int i = 0; i < 2; i++)
            #pragma unroll
            for (int j = 0; j < 8; j++)
                #pragma unroll
                for (int r = 0; r < 4; r++) acc[i][j][r] = 0.f;

        issue(0);
        issue(1);

        const uint32_t aoff = ((wm*32 + (lane & 15))*SAB + (lane >> 4)*8)*2;
        const uint32_t boff = (((lane & 7) + (lane >> 4)*8)*SAB +
                               ((lane >> 3) & 1)*8)*2 + (uint32_t)(wn*64)*SAB*2;

        #pragma unroll 1
        for (int kc = 0; kc < nk; kc++) {
            if (kc == nk - 1)
                asm volatile("cp.async.wait_group 0;\n" ::: "memory");
            else
                asm volatile("cp.async.wait_group 1;\n" ::: "memory");
            __syncthreads();
            issue(kc + 2);

            const uint32_t sb = sm0 + (uint32_t)(kc%3)*STAGE_B;
            #pragma unroll
            for (int ks = 0; ks < 2; ks++) {
                const uint32_t kbb = ks*32;
                uint32_t ah0[4], ah1[4], al0[4], al1[4];
                ldsm4(ah0, sb + aoff + kbb);
                ldsm4(ah1, sb + aoff + 16*SAB*2 + kbb);
                ldsm4(al0, sb + 10240 + aoff + kbb);
                ldsm4(al1, sb + 10240 + aoff + 16*SAB*2 + kbb);
                #pragma unroll
                for (int nt4 = 0; nt4 < 4; nt4++) {
                    uint32_t bh4[4], bl4[4];
                    const uint32_t bo = boff + (uint32_t)(nt4*16)*SAB*2 + kbb;
                    ldsm4(bh4, sb + 20480 + bo);
                    ldsm4(bl4, sb + 30720 + bo);
                    mma16816(acc[0][2*nt4],   ah0, bh4[0], bh4[1]);
                    mma16816(acc[0][2*nt4],   ah0, bl4[0], bl4[1]);
                    mma16816(acc[0][2*nt4],   al0, bh4[0], bh4[1]);
                    mma16816(acc[0][2*nt4+1], ah0, bh4[2], bh4[3]);
                    mma16816(acc[0][2*nt4+1], ah0, bl4[2], bl4[3]);
                    mma16816(acc[0][2*nt4+1], al0, bh4[2], bh4[3]);
                    mma16816(acc[1][2*nt4],   ah1, bh4[0], bh4[1]);
                    mma16816(acc[1][2*nt4],   ah1, bl4[0], bl4[1]);
                    mma16816(acc[1][2*nt4],   al1, bh4[0], bh4[1]);
                    mma16816(acc[1][2*nt4+1], ah1, bh4[2], bh4[3]);
                    mma16816(acc[1][2*nt4+1], ah1, bl4[2], bl4[3]);
                    mma16816(acc[1][2*nt4+1], al1, bh4[2], bh4[3]);
                }
            }
        }
    }
};

// Merged QKV GEMM with fused RoPE+RMSNorm epilogue for Q/K.
// blockIdx.z: 0 -> rope+rms -> bf16 hi/lo Q; 1 -> same -> K; 2 -> split V.
// BN=128 == head dim, so a tile is exactly one head: RMS row sums and RoPE
// pairs (c, c+64) are CTA-local. Q/K accumulators are staged to smem fp32,
// then each warp applies the bit-identical rope_rms math to 16 rows.
__global__ __launch_bounds__(256, 1) void gemm_qkv(
    const __nv_bfloat16* __restrict__ xh, const __nv_bfloat16* __restrict__ xl,
    const __nv_bfloat16* __restrict__ wh, const __nv_bfloat16* __restrict__ wl,
    const float* __restrict__ cosb, const float* __restrict__ sinb,
    __nv_bfloat16* __restrict__ qhi, __nv_bfloat16* __restrict__ qlo,
    __nv_bfloat16* __restrict__ khi, __nv_bfloat16* __restrict__ klo,
    __nv_bfloat16* __restrict__ Vhi, __nv_bfloat16* __restrict__ Vlo)
{
    extern __shared__ __nv_bfloat16 gsm[];
    const int z = blockIdx.z;
    const int bm = blockIdx.y * 128;
    const int bn = blockIdx.x * 128;
    const int h  = blockIdx.x;          // head index (BN == Dc)

    GemmCore core;
    core.run(xh, xl, wh + (size_t)z*Cc*Cc, wl + (size_t)z*Cc*Cc,
             bm, bn, Cc, cvta_s(gsm));

    if (z == 2) {
        #pragma unroll
        for (int i = 0; i < 2; i++) {
            const int r0 = bm + core.wm*32 + i*16 + core.g;
            #pragma unroll
            for (int j = 0; j < 8; j++) {
                const int col = bn + core.wn*64 + j*8 + 2*core.tg;
                uint32_t hp, lp;
                split_pair(core.acc[i][j][0], core.acc[i][j][1], hp, lp);
                *reinterpret_cast<uint32_t*>(Vhi + (size_t)r0*Cc + col) = hp;
                *reinterpret_cast<uint32_t*>(Vlo + (size_t)r0*Cc + col) = lp;
                split_pair(core.acc[i][j][2], core.acc[i][j][3], hp, lp);
                *reinterpret_cast<uint32_t*>(Vhi + (size_t)(r0+8)*Cc + col) = hp;
                *reinterpret_cast<uint32_t*>(Vlo + (size_t)(r0+8)*Cc + col) = lp;
            }
        }
        return;
    }

    // ---- fused RoPE + RMSNorm epilogue (z == 0 or 1) ----
    float* ft = reinterpret_cast<float*>(gsm);
    __syncthreads();   // mainloop smem reads complete before overwrite
    #pragma unroll
    for (int i = 0; i < 2; i++) {
        const int lr0 = core.wm*32 + i*16 + core.g;
        #pragma unroll
        for (int j = 0; j < 8; j++) {
            const int lc = core.wn*64 + j*8 + 2*core.tg;
            ft[lr0*FTS + lc]         = core.acc[i][j][0];
            ft[lr0*FTS + lc + 1]     = core.acc[i][j][1];
            ft[(lr0+8)*FTS + lc]     = core.acc[i][j][2];
            ft[(lr0+8)*FTS + lc + 1] = core.acc[i][j][3];
        }
    }
    __syncthreads();

    const int warp = threadIdx.x >> 5;
    const int lane = threadIdx.x & 31;
    __nv_bfloat16* ohi = (z == 0) ? qhi : khi;
    __nv_bfloat16* olo = (z == 0) ? qlo : klo;
    const int j = 2*lane;

    #pragma unroll 1
    for (int rr = 0; rr < 16; rr++) {
        const int row = warp*16 + rr;
        const int bt  = bm + row;
        const int t   = bt % Tc;
        const float* cpp = cosb + t*(Dc/2);
        const float* spp = sinb + t*(Dc/2);

        float2 x1 = *reinterpret_cast<const float2*>(&ft[row*FTS + j]);
        float2 x2 = *reinterpret_cast<const float2*>(&ft[row*FTS + 64 + j]);
        float2 cv = *reinterpret_cast<const float2*>(cpp + j);
        float2 sv = *reinterpret_cast<const float2*>(spp + j);

        float y1a = x1.x*cv.x + x2.x*sv.x;
        float y1b = x1.y*cv.y + x2.y*sv.y;
        float y2a = x2.x*cv.x - x1.x*sv.x;
        float y2b = x2.y*cv.y - x1.y*sv.y;

        float ss = y1a*y1a + y1b*y1b + y2a*y2a + y2b*y2b;
        #pragma unroll
        for (int off = 16; off; off >>= 1)
            ss += __shfl_xor_sync(0xffffffffu, ss, off);
        float sc = rsqrtf(ss * (1.f/128.f) + 1e-15f);
        if (z == 0) sc *= 0.12751745f;      // log2(e)/sqrt(128)

        const size_t roff = ((size_t)bt*Hc + h)*Dc;
        uint32_t hp, lp;
        split_pair(y1a*sc, y1b*sc, hp, lp);
        *reinterpret_cast<uint32_t*>(ohi + roff + j)      = hp;
        *reinterpret_cast<uint32_t*>(olo + roff + j)      = lp;
        split_pair(y2a*sc, y2b*sc, hp, lp);
        *reinterpret_cast<uint32_t*>(ohi + roff + 64 + j) = hp;
        *reinterpret_cast<uint32_t*>(olo + roff + 64 + j) = lp;
    }
}

// Plain GEMM (final O-projection), fp32 out.
__global__ __launch_bounds__(256, 1) void gemm_pre(
    const __nv_bfloat16* __restrict__ Ahi, const __nv_bfloat16* __restrict__ Alo,
    const __nv_bfloat16* __restrict__ Bhi, const __nv_bfloat16* __restrict__ Blo,
    float* __restrict__ C, int M, int N, int K)
{
    extern __shared__ __nv_bfloat16 gsm[];
    const int bm = blockIdx.y * 128;
    const int bn = blockIdx.x * 128;

    GemmCore core;
    core.run(Ahi, Alo, Bhi, Blo, bm, bn, K, cvta_s(gsm));

    #pragma unroll
    for (int i = 0; i < 2; i++) {
        const int r0 = bm + core.wm*32 + i*16 + core.g;
        #pragma unroll
        for (int j = 0; j < 8; j++) {
            const int col = bn + core.wn*64 + j*8 + 2*core.tg;
            *reinterpret_cast<float2*>(&C[(size_t)r0*N + col]) =
                make_float2(core.acc[i][j][0], core.acc[i][j][1]);
            *reinterpret_cast<float2*>(&C[(size_t)(r0+8)*N + col]) =
                make_float2(core.acc[i][j][2], core.acc[i][j][3]);
        }
    }
}

// ---------------------------------------------------------------------------
// MMA flash attention (causal) — R13: R11 body + LPT grid ordering.
// ---------------------------------------------------------------------------
#define QS 136
#define KVT (64*QS)
#define FSM_BYTES ((2*128*QS + 2*4*KVT) * 2)

__global__ __launch_bounds__(256, 1) void flash_mma(
    const __nv_bfloat16* __restrict__ Qhi_g, const __nv_bfloat16* __restrict__ Qlo_g,
    const __nv_bfloat16* __restrict__ Khi_g, const __nv_bfloat16* __restrict__ Klo_g,
    const __nv_bfloat16* __restrict__ Vhi_g, const __nv_bfloat16* __restrict__ Vlo_g,
    __nv_bfloat16* __restrict__ Ohi_g, __nv_bfloat16* __restrict__ Olo_g)
{
    extern __shared__ __nv_bfloat16 sb[];
    __nv_bfloat16* Qhi = sb;
    __nv_bfloat16* Qlo = Qhi + 128*QS;
    __nv_bfloat16* KVs = Qlo + 128*QS;

    const int qt = (int)gridDim.y - 1 - (int)blockIdx.y;   // LPT: heavy first
    const int bh = blockIdx.x;
    const int b = bh / Hc, h = bh % Hc;
    const int tid  = threadIdx.x;
    const int w    = tid >> 5;
    const int lane = tid & 31;
    const int g    = lane >> 2;
    const int tg   = lane & 3;
    const int rowstride = Hc * Dc;
    const int nkt = 2*qt + 2;

    {
        const size_t qoff = ((size_t)(b*Tc + qt*128) * Hc + h) * Dc;
        const __nv_bfloat16* qhg = Qhi_g + qoff;
        const __nv_bfloat16* qlg = Qlo_g + qoff;
        const uint32_t sQh = cvta_s(Qhi), sQl = cvta_s(Qlo);
        #pragma unroll
        for (int c = 0; c < 8; c++) {
            const int chunk = c*256 + tid;
            const int r = chunk >> 4, col = (chunk & 15)*8;
            cp16(sQh + (uint32_t)(r*QS + col)*2, qhg + r*rowstride + col);
            cp16(sQl + (uint32_t)(r*QS + col)*2, qlg + r*rowstride + col);
        }
    }

    auto issueKV = [&](int kt) {
        if (kt < nkt) {
            const size_t koff = ((size_t)(b*Tc + kt*64) * Hc + h) * Dc;
            const uint32_t st = cvta_s(KVs + (kt & 1)*4*KVT);
            const __nv_bfloat16* src[4] = {Khi_g + koff, Klo_g + koff,
                                           Vhi_g + koff, Vlo_g + koff};
            #pragma unroll
            for (int a = 0; a < 4; a++) {
                #pragma unroll
                for (int c = 0; c < 4; c++) {
                    const int chunk = c*256 + tid;
                    const int r = chunk >> 4, col = (chunk & 15)*8;
                    cp16(st + (uint32_t)(a*KVT + r*QS + col)*2,
                         src[a] + r*rowstride + col);
                }
            }
        }
        asm volatile("cp.async.commit_group;\n" ::: "memory");
    };

    issueKV(0);
    issueKV(1);

    const int q_off  = (w*16 + (lane & 15))*QS + (lane >> 4)*8;
    const int k_offr = ((lane & 7) + (lane >> 4)*8)*QS + ((lane >> 3) & 1)*8;
    const int v_offr = ((lane & 7) + ((lane >> 3) & 1)*8)*QS + (lane >> 4)*8;

    asm volatile("cp.async.wait_group 1;\n" ::: "memory");
    __syncthreads();
    uint32_t qfh[8][4], qfl[8][4];
    #pragma unroll
    for (int ks = 0; ks < 8; ks++) {
        ldsm4(qfh[ks], cvta_s(&Qhi[q_off + ks*16]));
        ldsm4(qfl[ks], cvta_s(&Qlo[q_off + ks*16]));
    }

    float o[16][4];
    #pragma unroll
    for (int i = 0; i < 16; i++)
        #pragma unroll
        for (int r = 0; r < 4; r++) o[i][r] = 0.f;
    float m0 = -1e30f, m1 = -1e30f, l0 = 0.f, l1 = 0.f;

    #pragma unroll 1
    for (int kt = 0; kt < nkt; kt++) {
        asm volatile("cp.async.wait_group 1;\n" ::: "memory");
        __syncthreads();

        __nv_bfloat16* Khi = KVs + (kt & 1)*4*KVT;
        __nv_bfloat16* Klo = Khi + KVT;
        __nv_bfloat16* Vhi = Klo + KVT;
        __nv_bfloat16* Vlo = Vhi + KVT;

        float s[8][4];
        #pragma unroll
        for (int nt = 0; nt < 8; nt++)
            #pragma unroll
            for (int r = 0; r < 4; r++) s[nt][r] = 0.f;

        #pragma unroll
        for (int ks = 0; ks < 8; ks++) {
            #pragma unroll
            for (int nt4 = 0; nt4 < 4; nt4++) {
                uint32_t bh4[4], bl4[4];
                ldsm4(bh4, cvta_s(&Khi[nt4*16*QS + k_offr + ks*16]));
                ldsm4(bl4, cvta_s(&Klo[nt4*16*QS + k_offr + ks*16]));
                mma16816(s[2*nt4],   qfh[ks], bh4[0], bh4[1]);
                mma16816(s[2*nt4],   qfh[ks], bl4[0], bl4[1]);
                mma16816(s[2*nt4],   qfl[ks], bh4[0], bh4[1]);
                mma16816(s[2*nt4+1], qfh[ks], bh4[2], bh4[3]);
                mma16816(s[2*nt4+1], qfh[ks], bl4[2], bl4[3]);
                mma16816(s[2*nt4+1], qfl[ks], bh4[2], bh4[3]);
            }
        }

        if (kt >= nkt - 2) {
            const int gq0 = qt*128 + w*16 + g;
            const int gq1 = gq0 + 8;
            #pragma unroll
            for (int nt = 0; nt < 8; nt++) {
                const int gk = kt*64 + nt*8 + 2*tg;
                if (gk     > gq0) s[nt][0] = -1e30f;
                if (gk + 1 > gq0) s[nt][1] = -1e30f;
                if (gk     > gq1) s[nt][2] = -1e30f;
                if (gk + 1 > gq1) s[nt][3] = -1e30f;
            }
        }

        float mx0 = -1e30f, mx1 = -1e30f;
        #pragma unroll
        for (int nt = 0; nt < 8; nt++) {
            mx0 = fmaxf(mx0, fmaxf(s[nt][0], s[nt][1]));
            mx1 = fmaxf(mx1, fmaxf(s[nt][2], s[nt][3]));
        }
        #pragma unroll
        for (int off = 1; off <= 2; off <<= 1) {
            mx0 = fmaxf(mx0, __shfl_xor_sync(0xffffffffu, mx0, off));
            mx1 = fmaxf(mx1, __shfl_xor_sync(0xffffffffu, mx1, off));
        }
        const float mn0 = fmaxf(m0, mx0);
        const float mn1 = fmaxf(m1, mx1);
        const float a0 = ex2(m0 - mn0);
        const float a1 = ex2(m1 - mn1);
        m0 = mn0; m1 = mn1;

        float rs0 = 0.f, rs1 = 0.f;
        #pragma unroll
        for (int nt = 0; nt < 8; nt++) {
            s[nt][0] = ex2(s[nt][0] - mn0);
            s[nt][1] = ex2(s[nt][1] - mn0);
            s[nt][2] = ex2(s[nt][2] - mn1);
            s[nt][3] = ex2(s[nt][3] - mn1);
            rs0 += s[nt][0] + s[nt][1];
            rs1 += s[nt][2] + s[nt][3];
        }
        #pragma unroll
        for (int off = 1; off <= 2; off <<= 1) {
            rs0 += __shfl_xor_sync(0xffffffffu, rs0, off);
            rs1 += __shfl_xor_sync(0xffffffffu, rs1, off);
        }
        l0 = l0*a0 + rs0;
        l1 = l1*a1 + rs1;
        #pragma unroll
        for (int dt = 0; dt < 16; dt++) {
            o[dt][0] *= a0; o[dt][1] *= a0;
            o[dt][2] *= a1; o[dt][3] *= a1;
        }

        #pragma unroll
        for (int ks2 = 0; ks2 < 4; ks2++) {
            uint32_t pha[4], pla[4];
            #pragma unroll
            for (int half = 0; half < 2; half++) {
                split_pair(s[2*ks2 + half][0], s[2*ks2 + half][1],
                           pha[0 + 2*half], pla[0 + 2*half]);
                split_pair(s[2*ks2 + half][2], s[2*ks2 + half][3],
                           pha[1 + 2*half], pla[1 + 2*half]);
            }
            #pragma unroll
            for (int dt4 = 0; dt4 < 8; dt4++) {
                uint32_t vh4[4], vl4[4];
                ldsm4t(vh4, cvta_s(&Vhi[ks2*16*QS + v_offr + dt4*16]));
                ldsm4t(vl4, cvta_s(&Vlo[ks2*16*QS + v_offr + dt4*16]));
                mma16816(o[2*dt4],   pha, vh4[0], vh4[1]);
                mma16816(o[2*dt4],   pha, vl4[0], vl4[1]);
                mma16816(o[2*dt4],   pla, vh4[0], vh4[1]);
                mma16816(o[2*dt4+1], pha, vh4[2], vh4[3]);
                mma16816(o[2*dt4+1], pha, vl4[2], vl4[3]);
                mma16816(o[2*dt4+1], pla, vh4[2], vh4[3]);
            }
        }

        __syncthreads();
        issueKV(kt + 2);
    }

    const float inv0 = 1.f / l0;
    const float inv1 = 1.f / l1;
    const size_t obase = ((size_t)(b*Tc + qt*128) * Hc + h) * Dc;
    const int r0 = w*16 + g;
    #pragma unroll
    for (int dt = 0; dt < 16; dt++) {
        const int col = dt*8 + 2*tg;
        uint32_t hp, lp;
        split_pair(o[dt][0]*inv0, o[dt][1]*inv0, hp, lp);
        *reinterpret_cast<uint32_t*>(Ohi_g + obase + (size_t)r0*rowstride + col) = hp;
        *reinterpret_cast<uint32_t*>(Olo_g + obase + (size_t)r0*rowstride + col) = lp;
        split_pair(o[dt][2]*inv1, o[dt][3]*inv1, hp, lp);
        *reinterpret_cast<uint32_t*>(Ohi_g + obase + (size_t)(r0+8)*rowstride + col) = hp;
        *reinterpret_cast<uint32_t*>(Olo_g + obase + (size_t)(r0+8)*rowstride + col) = lp;
    }
}

// ---------------------------------------------------------------------------
extern "C" void kernel_launch(void* const* d_in, const int* in_sizes, int n_in,
                              void* d_out, int out_size)
{
    const float* x  = (const float*)d_in[0];
    const float* cs = (const float*)d_in[1];
    const float* sn = (const float*)d_in[2];
    const float* Wq = (const float*)d_in[3];
    const float* Wk = (const float*)d_in[4];
    const float* Wv = (const float*)d_in[5];
    const float* Wo = (const float*)d_in[6];
    float* out = (float*)d_out;

    __nv_bfloat16 *xh, *xl, *wh, *wl, *qh, *ql, *kh, *kl, *vh, *vl, *oh, *ol;
    cudaGetSymbolAddress((void**)&xh, g_xhi);
    cudaGetSymbolAddress((void**)&xl, g_xlo);
    cudaGetSymbolAddress((void**)&wh, g_whi);
    cudaGetSymbolAddress((void**)&wl, g_wlo);
    cudaGetSymbolAddress((void**)&qh, g_qhi);
    cudaGetSymbolAddress((void**)&ql, g_qlo);
    cudaGetSymbolAddress((void**)&kh, g_khi);
    cudaGetSymbolAddress((void**)&kl, g_klo);
    cudaGetSymbolAddress((void**)&vh, g_vhi);
    cudaGetSymbolAddress((void**)&vl, g_vlo);
    cudaGetSymbolAddress((void**)&oh, g_ohi);
    cudaGetSymbolAddress((void**)&ol, g_olo);

    cudaFuncSetAttribute(flash_mma,
                         cudaFuncAttributeMaxDynamicSharedMemorySize, FSM_BYTES);
    cudaFuncSetAttribute(gemm_qkv,
                         cudaFuncAttributeMaxDynamicSharedMemorySize, GSM_BYTES);
    cudaFuncSetAttribute(gemm_pre,
                         cudaFuncAttributeMaxDynamicSharedMemorySize, GSM_BYTES);

    const int NX = Mrows*Cc;
    const int NW = Cc*Cc;

    split_f32<<<NX/4/256, 256>>>(x, xh, xl, NX);
    split_w4<<<dim3(NW/4/256, 4), 256>>>(Wq, Wk, Wv, Wo, wh, wl);

    gemm_qkv<<<dim3(Cc/128, Mrows/128, 3), 256, GSM_BYTES>>>(
        xh, xl, wh, wl, cs, sn, qh, ql, kh, kl, vh, vl);

    flash_mma<<<dim3(Bc*Hc, Tc/128), 256, FSM_BYTES>>>(qh, ql, kh, kl, vh, vl, oh, ol);

    gemm_pre<<<dim3(Cc/128, Mrows/128), 256, GSM_BYTES>>>(
        oh, ol, wh + 3*NW, wl + 3*NW, out, Mrows, Cc, Cc);
}

// round 15
// speedup vs baseline: 1.0256x; 1.0256x over previous
#include <cuda_runtime.h>
#include <cuda_bf16.h>
#include <cstdint>
#include <math.h>

#define Bc 4
#define Tc 2048
#define Cc 768
#define Hc 6
#define Dc 128
#define Mrows (Bc*Tc)

// fp32 scratch
__device__ float g_Q[Mrows*Cc];
__device__ float g_K[Mrows*Cc];
// bf16 split scratch
__device__ __align__(16) __nv_bfloat16 g_xhi[Mrows*Cc];
__device__ __align__(16) __nv_bfloat16 g_xlo[Mrows*Cc];
__device__ __align__(16) __nv_bfloat16 g_whi[4*Cc*Cc];
__device__ __align__(16) __nv_bfloat16 g_wlo[4*Cc*Cc];
__device__ __align__(16) __nv_bfloat16 g_qhi[Mrows*Cc];
__device__ __align__(16) __nv_bfloat16 g_qlo[Mrows*Cc];
__device__ __align__(16) __nv_bfloat16 g_khi[Mrows*Cc];
__device__ __align__(16) __nv_bfloat16 g_klo[Mrows*Cc];
__device__ __align__(16) __nv_bfloat16 g_vhi[Mrows*Cc];
__device__ __align__(16) __nv_bfloat16 g_vlo[Mrows*Cc];
__device__ __align__(16) __nv_bfloat16 g_ohi[Mrows*Cc];
__device__ __align__(16) __nv_bfloat16 g_olo[Mrows*Cc];

// ---------------------------------------------------------------------------
// helpers
// ---------------------------------------------------------------------------
__device__ __forceinline__ void mma16816(float* c, const uint32_t* a,
                                         uint32_t b0, uint32_t b1) {
    asm volatile(
        "mma.sync.aligned.m16n8k16.row.col.f32.bf16.bf16.f32 "
        "{%0,%1,%2,%3}, {%4,%5,%6,%7}, {%8,%9}, {%0,%1,%2,%3};\n"
        : "+f"(c[0]), "+f"(c[1]), "+f"(c[2]), "+f"(c[3])
        : "r"(a[0]), "r"(a[1]), "r"(a[2]), "r"(a[3]), "r"(b0), "r"(b1));
}

__device__ __forceinline__ uint32_t pack_bf16x2_rn(float f0, float f1) {
    uint32_t r;
    asm("cvt.rn.bf16x2.f32 %0, %1, %2;\n" : "=r"(r) : "f"(f1), "f"(f0));
    return r;
}

__device__ __forceinline__ uint32_t cvta_s(const void* p) {
    return (uint32_t)__cvta_generic_to_shared(p);
}

__device__ __forceinline__ void ldsm4(uint32_t* r, uint32_t a) {
    asm volatile("ldmatrix.sync.aligned.m8n8.x4.shared.b16 {%0,%1,%2,%3}, [%4];"
        : "=r"(r[0]), "=r"(r[1]), "=r"(r[2]), "=r"(r[3]) : "r"(a));
}

__device__ __forceinline__ void ldsm4t(uint32_t* r, uint32_t a) {
    asm volatile("ldmatrix.sync.aligned.m8n8.x4.trans.shared.b16 {%0,%1,%2,%3}, [%4];"
        : "=r"(r[0]), "=r"(r[1]), "=r"(r[2]), "=r"(r[3]) : "r"(a));
}

__device__ __forceinline__ float ex2(float x) {
    float y;
    asm("ex2.approx.ftz.f32 %0, %1;" : "=f"(y) : "f"(x));
    return y;
}

__device__ __forceinline__ void cp16(uint32_t dst, const void* src) {
    asm volatile("cp.async.cg.shared.global [%0], [%1], 16;\n"
                 :: "r"(dst), "l"(src) : "memory");
}

__device__ __forceinline__ void split_pair(
    float f0, float f1, uint32_t& hp, uint32_t& lp)
{
    uint32_t h0 = __float_as_uint(f0) & 0xFFFF0000u;
    uint32_t h1 = __float_as_uint(f1) & 0xFFFF0000u;
    hp = (h0 >> 16) | h1;
    lp = pack_bf16x2_rn(f0 - __uint_as_float(h0), f1 - __uint_as_float(h1));
}

__device__ __forceinline__ void split4(
    __nv_bfloat16* hi, __nv_bfloat16* lo, int idx, float4 v)
{
    float f[4] = {v.x, v.y, v.z, v.w};
    #pragma unroll
    for (int p = 0; p < 2; p++) {
        uint32_t hp, lp;
        split_pair(f[2*p], f[2*p+1], hp, lp);
        *reinterpret_cast<uint32_t*>(hi + idx + 2*p) = hp;
        *reinterpret_cast<uint32_t*>(lo + idx + 2*p) = lp;
    }
}

// ---------------------------------------------------------------------------
// split passes
// ---------------------------------------------------------------------------
__global__ __launch_bounds__(256) void split_f32(
    const float* __restrict__ src, __nv_bfloat16* __restrict__ hi,
    __nv_bfloat16* __restrict__ lo, int n)
{
    int i = (blockIdx.x*256 + threadIdx.x)*4;
    if (i < n)
        split4(hi, lo, i, *reinterpret_cast<const float4*>(src + i));
}

__global__ __launch_bounds__(256) void split_w4(
    const float* __restrict__ w0, const float* __restrict__ w1,
    const float* __restrict__ w2, const float* __restrict__ w3,
    __nv_bfloat16* __restrict__ hi, __nv_bfloat16* __restrict__ lo)
{
    const int z = blockIdx.y;
    const float* src = (z == 0) ? w0 : (z == 1) ? w1 : (z == 2) ? w2 : w3;
    const int nw = Cc*Cc;
    int i = (blockIdx.x*256 + threadIdx.x)*4;
    if (i < nw)
        split4(hi + (size_t)z*nw, lo + (size_t)z*nw, i,
               *reinterpret_cast<const float4*>(src + i));
}

// ---------------------------------------------------------------------------
// pipelined bf16 3-pass GEMM core (NT)
// ---------------------------------------------------------------------------
#define SAB 40
#define STAGE_B 40960
#define GSM_BYTES (3*STAGE_B)

struct GemmCore {
    float acc[2][8][4];
    int wm, wn, g, tg;

    __device__ __forceinline__ void run(
        const __nv_bfloat16* Ahi, const __nv_bfloat16* Alo,
        const __nv_bfloat16* Bhi, const __nv_bfloat16* Blo,
        int bm, int bn, int K, uint32_t sm0)
    {
        const int tid  = threadIdx.x;
        const int warp = tid >> 5, lane = tid & 31;
        wm = warp >> 1; wn = warp & 1;
        g  = lane >> 2; tg = lane & 3;

        const int lrow = tid >> 1;
        const int lk   = (tid & 1) * 16;

        const __nv_bfloat16* pAh = Ahi + (size_t)(bm + lrow)*K + lk;
        const __nv_bfloat16* pAl = Alo + (size_t)(bm + lrow)*K + lk;
        const __nv_bfloat16* pBh = Bhi + (size_t)(bn + lrow)*K + lk;
        const __nv_bfloat16* pBl = Blo + (size_t)(bn + lrow)*K + lk;
        const uint32_t dbase = sm0 + (uint32_t)(lrow*SAB + lk)*2;

        const int nk = K / 32;

        auto issue = [&](int kc) {
            if (kc < nk) {
                const int ko = kc*32;
                const uint32_t d = dbase + (uint32_t)(kc%3)*STAGE_B;
                cp16(d,             pAh + ko);  cp16(d + 16,         pAh + ko + 8);
                cp16(d + 10240,     pAl + ko);  cp16(d + 10240 + 16, pAl + ko + 8);
                cp16(d + 20480,     pBh + ko);  cp16(d + 20480 + 16, pBh + ko + 8);
                cp16(d + 30720,     pBl + ko);  cp16(d + 30720 + 16, pBl + ko + 8);
            }
            asm volatile("cp.async.commit_group;\n" ::: "memory");
        };

        #pragma unroll
        for (int i = 0; i < 2; i++)
            #pragma unroll
            for (int j = 0; j < 8; j++)
                #pragma unroll
                for (int r = 0; r < 4; r++) acc[i][j][r] = 0.f;

        issue(0);
        issue(1);

        const uint32_t aoff = ((wm*32 + (lane & 15))*SAB + (lane >> 4)*8)*2;
        const uint32_t boff = (((lane & 7) + (lane >> 4)*8)*SAB +
                               ((lane >> 3) & 1)*8)*2 + (uint32_t)(wn*64)*SAB*2;

        #pragma unroll 1
        for (int kc = 0; kc < nk; kc++) {
            if (kc == nk - 1)
                asm volatile("cp.async.wait_group 0;\n" ::: "memory");
            else
                asm volatile("cp.async.wait_group 1;\n" ::: "memory");
            __syncthreads();
            issue(kc + 2);

            const uint32_t sb = sm0 + (uint32_t)(kc%3)*STAGE_B;
            #pragma unroll
            for (int ks = 0; ks < 2; ks++) {
                const uint32_t kbb = ks*32;
                uint32_t ah0[4], ah1[4], al0[4], al1[4];
                ldsm4(ah0, sb + aoff + kbb);
                ldsm4(ah1, sb + aoff + 16*SAB*2 + kbb);
                ldsm4(al0, sb + 10240 + aoff + kbb);
                ldsm4(al1, sb + 10240 + aoff + 16*SAB*2 + kbb);
                #pragma unroll
                for (int nt4 = 0; nt4 < 4; nt4++) {
                    uint32_t bh4[4], bl4[4];
                    const uint32_t bo = boff + (uint32_t)(nt4*16)*SAB*2 + kbb;
                    ldsm4(bh4, sb + 20480 + bo);
                    ldsm4(bl4, sb + 30720 + bo);
                    mma16816(acc[0][2*nt4],   ah0, bh4[0], bh4[1]);
                    mma16816(acc[0][2*nt4],   ah0, bl4[0], bl4[1]);
                    mma16816(acc[0][2*nt4],   al0, bh4[0], bh4[1]);
                    mma16816(acc[0][2*nt4+1], ah0, bh4[2], bh4[3]);
                    mma16816(acc[0][2*nt4+1], ah0, bl4[2], bl4[3]);
                    mma16816(acc[0][2*nt4+1], al0, bh4[2], bh4[3]);
                    mma16816(acc[1][2*nt4],   ah1, bh4[0], bh4[1]);
                    mma16816(acc[1][2*nt4],   ah1, bl4[0], bl4[1]);
                    mma16816(acc[1][2*nt4],   al1, bh4[0], bh4[1]);
                    mma16816(acc[1][2*nt4+1], ah1, bh4[2], bh4[3]);
                    mma16816(acc[1][2*nt4+1], ah1, bl4[2], bl4[3]);
                    mma16816(acc[1][2*nt4+1], al1, bh4[2], bh4[3]);
                }
            }
        }
    }
};

// Merged QKV GEMM: blockIdx.z selects weight + destination.
__global__ __launch_bounds__(256, 1) void gemm_qkv(
    const __nv_bfloat16* __restrict__ xh, const __nv_bfloat16* __restrict__ xl,
    const __nv_bfloat16* __restrict__ wh, const __nv_bfloat16* __restrict__ wl,
    float* __restrict__ Qo, float* __restrict__ Ko,
    __nv_bfloat16* __restrict__ Vhi, __nv_bfloat16* __restrict__ Vlo)
{
    extern __shared__ __nv_bfloat16 gsm[];
    const int z = blockIdx.z;
    const int bm = blockIdx.y * 128;
    const int bn = blockIdx.x * 128;

    GemmCore core;
    core.run(xh, xl, wh + (size_t)z*Cc*Cc, wl + (size_t)z*Cc*Cc,
             bm, bn, Cc, cvta_s(gsm));

    float* C = (z == 0) ? Qo : Ko;
    #pragma unroll
    for (int i = 0; i < 2; i++) {
        const int r0 = bm + core.wm*32 + i*16 + core.g;
        #pragma unroll
        for (int j = 0; j < 8; j++) {
            const int col = bn + core.wn*64 + j*8 + 2*core.tg;
            if (z == 2) {
                uint32_t hp, lp;
                split_pair(core.acc[i][j][0], core.acc[i][j][1], hp, lp);
                *reinterpret_cast<uint32_t*>(Vhi + (size_t)r0*Cc + col) = hp;
                *reinterpret_cast<uint32_t*>(Vlo + (size_t)r0*Cc + col) = lp;
                split_pair(core.acc[i][j][2], core.acc[i][j][3], hp, lp);
                *reinterpret_cast<uint32_t*>(Vhi + (size_t)(r0+8)*Cc + col) = hp;
                *reinterpret_cast<uint32_t*>(Vlo + (size_t)(r0+8)*Cc + col) = lp;
            } else {
                *reinterpret_cast<float2*>(&C[(size_t)r0*Cc + col]) =
                    make_float2(core.acc[i][j][0], core.acc[i][j][1]);
                *reinterpret_cast<float2*>(&C[(size_t)(r0+8)*Cc + col]) =
                    make_float2(core.acc[i][j][2], core.acc[i][j][3]);
            }
        }
    }
}

// Plain GEMM (final O-projection), fp32 out.
__global__ __launch_bounds__(256, 1) void gemm_pre(
    const __nv_bfloat16* __restrict__ Ahi, const __nv_bfloat16* __restrict__ Alo,
    const __nv_bfloat16* __restrict__ Bhi, const __nv_bfloat16* __restrict__ Blo,
    float* __restrict__ C, int M, int N, int K)
{
    extern __shared__ __nv_bfloat16 gsm[];
    const int bm = blockIdx.y * 128;
    const int bn = blockIdx.x * 128;

    GemmCore core;
    core.run(Ahi, Alo, Bhi, Blo, bm, bn, K, cvta_s(gsm));

    #pragma unroll
    for (int i = 0; i < 2; i++) {
        const int r0 = bm + core.wm*32 + i*16 + core.g;
        #pragma unroll
        for (int j = 0; j < 8; j++) {
            const int col = bn + core.wn*64 + j*8 + 2*core.tg;
            *reinterpret_cast<float2*>(&C[(size_t)r0*N + col]) =
                make_float2(core.acc[i][j][0], core.acc[i][j][1]);
            *reinterpret_cast<float2*>(&C[(size_t)(r0+8)*N + col]) =
                make_float2(core.acc[i][j][2], core.acc[i][j][3]);
        }
    }
}

// ---------------------------------------------------------------------------
// Fused RoPE + RMSNorm -> pre-scaled bf16 hi/lo (standalone, as in R13)
// ---------------------------------------------------------------------------
__global__ __launch_bounds__(384) void rope_rms_split(
    const float* __restrict__ Q, const float* __restrict__ K,
    const float* __restrict__ cosb, const float* __restrict__ sinb,
    __nv_bfloat16* __restrict__ qhi, __nv_bfloat16* __restrict__ qlo,
    __nv_bfloat16* __restrict__ khi, __nv_bfloat16* __restrict__ klo)
{
    const int bt   = blockIdx.x;
    const int t    = bt % Tc;
    const int w    = threadIdx.x >> 5;
    const int lane = threadIdx.x & 31;
    const bool isQ = (w < Hc);
    const int h = isQ ? w : (w - Hc);
    const size_t roff = ((size_t)bt * Hc + h) * Dc;
    const float* row = (isQ ? Q : K) + roff;
    __nv_bfloat16* ohi = (isQ ? qhi : khi) + roff;
    __nv_bfloat16* olo = (isQ ? qlo : klo) + roff;
    const float* cp = cosb + t * (Dc/2);
    const float* sp = sinb + t * (Dc/2);

    const int j = 2*lane;
    float2 x1 = *reinterpret_cast<const float2*>(row + j);
    float2 x2 = *reinterpret_cast<const float2*>(row + 64 + j);
    float2 cv = *reinterpret_cast<const float2*>(cp + j);
    float2 sv = *reinterpret_cast<const float2*>(sp + j);

    float y1a = x1.x*cv.x + x2.x*sv.x;
    float y1b = x1.y*cv.y + x2.y*sv.y;
    float y2a = x2.x*cv.x - x1.x*sv.x;
    float y2b = x2.y*cv.y - x1.y*sv.y;

    float ss = y1a*y1a + y1b*y1b + y2a*y2a + y2b*y2b;
    #pragma unroll
    for (int off = 16; off; off >>= 1)
        ss += __shfl_xor_sync(0xffffffffu, ss, off);
    float sc = rsqrtf(ss * (1.f/128.f) + 1e-15f);
    if (isQ) sc *= 0.12751745f;        // log2(e)/sqrt(128)

    uint32_t hp, lp;
    split_pair(y1a*sc, y1b*sc, hp, lp);
    *reinterpret_cast<uint32_t*>(ohi + j)      = hp;
    *reinterpret_cast<uint32_t*>(olo + j)      = lp;
    split_pair(y2a*sc, y2b*sc, hp, lp);
    *reinterpret_cast<uint32_t*>(ohi + 64 + j) = hp;
    *reinterpret_cast<uint32_t*>(olo + 64 + j) = lp;
}

// ---------------------------------------------------------------------------
// MMA flash attention (causal) — R13 structure + STATIC-MAX softmax.
// RMSNorm bounds every score: s = (C2*qhat)·khat <= C2*128 = 16.3222, so
// p = ex2(s - SMAX) with constant SMAX needs no running max, no o-rescale,
// and l reduces across the quad once in the epilogue.
// ---------------------------------------------------------------------------
#define QS 136
#define KVT (64*QS)
#define FSM_BYTES ((2*128*QS + 2*4*KVT) * 2)
#define SMAX 16.3223f

__global__ __launch_bounds__(256, 1) void flash_mma(
    const __nv_bfloat16* __restrict__ Qhi_g, const __nv_bfloat16* __restrict__ Qlo_g,
    const __nv_bfloat16* __restrict__ Khi_g, const __nv_bfloat16* __restrict__ Klo_g,
    const __nv_bfloat16* __restrict__ Vhi_g, const __nv_bfloat16* __restrict__ Vlo_g,
    __nv_bfloat16* __restrict__ Ohi_g, __nv_bfloat16* __restrict__ Olo_g)
{
    extern __shared__ __nv_bfloat16 sb[];
    __nv_bfloat16* Qhi = sb;
    __nv_bfloat16* Qlo = Qhi + 128*QS;
    __nv_bfloat16* KVs = Qlo + 128*QS;

    const int qt = (int)gridDim.y - 1 - (int)blockIdx.y;   // LPT: heavy first
    const int bh = blockIdx.x;
    const int b = bh / Hc, h = bh % Hc;
    const int tid  = threadIdx.x;
    const int w    = tid >> 5;
    const int lane = tid & 31;
    const int g    = lane >> 2;
    const int tg   = lane & 3;
    const int rowstride = Hc * Dc;
    const int nkt = 2*qt + 2;

    {
        const size_t qoff = ((size_t)(b*Tc + qt*128) * Hc + h) * Dc;
        const __nv_bfloat16* qhg = Qhi_g + qoff;
        const __nv_bfloat16* qlg = Qlo_g + qoff;
        const uint32_t sQh = cvta_s(Qhi), sQl = cvta_s(Qlo);
        #pragma unroll
        for (int c = 0; c < 8; c++) {
            const int chunk = c*256 + tid;
            const int r = chunk >> 4, col = (chunk & 15)*8;
            cp16(sQh + (uint32_t)(r*QS + col)*2, qhg + r*rowstride + col);
            cp16(sQl + (uint32_t)(r*QS + col)*2, qlg + r*rowstride + col);
        }
    }

    auto issueKV = [&](int kt) {
        if (kt < nkt) {
            const size_t koff = ((size_t)(b*Tc + kt*64) * Hc + h) * Dc;
            const uint32_t st = cvta_s(KVs + (kt & 1)*4*KVT);
            const __nv_bfloat16* src[4] = {Khi_g + koff, Klo_g + koff,
                                           Vhi_g + koff, Vlo_g + koff};
            #pragma unroll
            for (int a = 0; a < 4; a++) {
                #pragma unroll
                for (int c = 0; c < 4; c++) {
                    const int chunk = c*256 + tid;
                    const int r = chunk >> 4, col = (chunk & 15)*8;
                    cp16(st + (uint32_t)(a*KVT + r*QS + col)*2,
                         src[a] + r*rowstride + col);
                }
            }
        }
        asm volatile("cp.async.commit_group;\n" ::: "memory");
    };

    issueKV(0);
    issueKV(1);

    const int q_off  = (w*16 + (lane & 15))*QS + (lane >> 4)*8;
    const int k_offr = ((lane & 7) + (lane >> 4)*8)*QS + ((lane >> 3) & 1)*8;
    const int v_offr = ((lane & 7) + ((lane >> 3) & 1)*8)*QS + (lane >> 4)*8;

    asm volatile("cp.async.wait_group 1;\n" ::: "memory");
    __syncthreads();
    uint32_t qfh[8][4], qfl[8][4];
    #pragma unroll
    for (int ks = 0; ks < 8; ks++) {
        ldsm4(qfh[ks], cvta_s(&Qhi[q_off + ks*16]));
        ldsm4(qfl[ks], cvta_s(&Qlo[q_off + ks*16]));
    }

    float o[16][4];
    #pragma unroll
    for (int i = 0; i < 16; i++)
        #pragma unroll
        for (int r = 0; r < 4; r++) o[i][r] = 0.f;
    float l0 = 0.f, l1 = 0.f;      // thread-local partial row sums

    #pragma unroll 1
    for (int kt = 0; kt < nkt; kt++) {
        asm volatile("cp.async.wait_group 1;\n" ::: "memory");
        __syncthreads();

        __nv_bfloat16* Khi = KVs + (kt & 1)*4*KVT;
        __nv_bfloat16* Klo = Khi + KVT;
        __nv_bfloat16* Vhi = Klo + KVT;
        __nv_bfloat16* Vlo = Vhi + KVT;

        // S = Q K^T (16 x 64 per warp), 3-pass
        float s[8][4];
        #pragma unroll
        for (int nt = 0; nt < 8; nt++)
            #pragma unroll
            for (int r = 0; r < 4; r++) s[nt][r] = 0.f;

        #pragma unroll
        for (int ks = 0; ks < 8; ks++) {
            #pragma unroll
            for (int nt4 = 0; nt4 < 4; nt4++) {
                uint32_t bh4[4], bl4[4];
                ldsm4(bh4, cvta_s(&Khi[nt4*16*QS + k_offr + ks*16]));
                ldsm4(bl4, cvta_s(&Klo[nt4*16*QS + k_offr + ks*16]));
                mma16816(s[2*nt4],   qfh[ks], bh4[0], bh4[1]);
                mma16816(s[2*nt4],   qfh[ks], bl4[0], bl4[1]);
                mma16816(s[2*nt4],   qfl[ks], bh4[0], bh4[1]);
                mma16816(s[2*nt4+1], qfh[ks], bh4[2], bh4[3]);
                mma16816(s[2*nt4+1], qfh[ks], bl4[2], bl4[3]);
                mma16816(s[2*nt4+1], qfl[ks], bh4[2], bh4[3]);
            }
        }

        if (kt >= nkt - 2) {
            const int gq0 = qt*128 + w*16 + g;
            const int gq1 = gq0 + 8;
            #pragma unroll
            for (int nt = 0; nt < 8; nt++) {
                const int gk = kt*64 + nt*8 + 2*tg;
                if (gk     > gq0) s[nt][0] = -1e30f;
                if (gk + 1 > gq0) s[nt][1] = -1e30f;
                if (gk     > gq1) s[nt][2] = -1e30f;
                if (gk + 1 > gq1) s[nt][3] = -1e30f;
            }
        }

        // static-max softmax: p = ex2(s - SMAX); accumulate partial sums
        #pragma unroll
        for (int nt = 0; nt < 8; nt++) {
            s[nt][0] = ex2(s[nt][0] - SMAX);
            s[nt][1] = ex2(s[nt][1] - SMAX);
            s[nt][2] = ex2(s[nt][2] - SMAX);
            s[nt][3] = ex2(s[nt][3] - SMAX);
            l0 += s[nt][0] + s[nt][1];
            l1 += s[nt][2] + s[nt][3];
        }

        // O += P V  (P hi/lo split from fp32; 3-pass compensation)
        #pragma unroll
        for (int ks2 = 0; ks2 < 4; ks2++) {
            uint32_t pha[4], pla[4];
            #pragma unroll
            for (int half = 0; half < 2; half++) {
                split_pair(s[2*ks2 + half][0], s[2*ks2 + half][1],
                           pha[0 + 2*half], pla[0 + 2*half]);
                split_pair(s[2*ks2 + half][2], s[2*ks2 + half][3],
                           pha[1 + 2*half], pla[1 + 2*half]);
            }
            #pragma unroll
            for (int dt4 = 0; dt4 < 8; dt4++) {
                uint32_t vh4[4], vl4[4];
                ldsm4t(vh4, cvta_s(&Vhi[ks2*16*QS + v_offr + dt4*16]));
                ldsm4t(vl4, cvta_s(&Vlo[ks2*16*QS + v_offr + dt4*16]));
                mma16816(o[2*dt4],   pha, vh4[0], vh4[1]);
                mma16816(o[2*dt4],   pha, vl4[0], vl4[1]);
                mma16816(o[2*dt4],   pla, vh4[0], vh4[1]);
                mma16816(o[2*dt4+1], pha, vh4[2], vh4[3]);
                mma16816(o[2*dt4+1], pha, vl4[2], vl4[3]);
                mma16816(o[2*dt4+1], pla, vh4[2], vh4[3]);
            }
        }

        __syncthreads();
        issueKV(kt + 2);
    }

    // epilogue: reduce l across the quad, then (O / l) -> bf16 hi/lo split
    #pragma unroll
    for (int off = 1; off <= 2; off <<= 1) {
        l0 += __shfl_xor_sync(0xffffffffu, l0, off);
        l1 += __shfl_xor_sync(0xffffffffu, l1, off);
    }
    const float inv0 = 1.f / l0;
    const float inv1 = 1.f / l1;
    const size_t obase = ((size_t)(b*Tc + qt*128) * Hc + h) * Dc;
    const int r0 = w*16 + g;
    #pragma unroll
    for (int dt = 0; dt < 16; dt++) {
        const int col = dt*8 + 2*tg;
        uint32_t hp, lp;
        split_pair(o[dt][0]*inv0, o[dt][1]*inv0, hp, lp);
        *reinterpret_cast<uint32_t*>(Ohi_g + obase + (size_t)r0*rowstride + col) = hp;
        *reinterpret_cast<uint32_t*>(Olo_g + obase + (size_t)r0*rowstride + col) = lp;
        split_pair(o[dt][2]*inv1, o[dt][3]*inv1, hp, lp);
        *reinterpret_cast<uint32_t*>(Ohi_g + obase + (size_t)(r0+8)*rowstride + col) = hp;
        *reinterpret_cast<uint32_t*>(Olo_g + obase + (size_t)(r0+8)*rowstride + col) = lp;
    }
}

// ---------------------------------------------------------------------------
extern "C" void kernel_launch(void* const* d_in, const int* in_sizes, int n_in,
                              void* d_out, int out_size)
{
    const float* x  = (const float*)d_in[0];
    const float* cs = (const float*)d_in[1];
    const float* sn = (const float*)d_in[2];
    const float* Wq = (const float*)d_in[3];
    const float* Wk = (const float*)d_in[4];
    const float* Wv = (const float*)d_in[5];
    const float* Wo = (const float*)d_in[6];
    float* out = (float*)d_out;

    float *Qp, *Kp;
    cudaGetSymbolAddress((void**)&Qp, g_Q);
    cudaGetSymbolAddress((void**)&Kp, g_K);
    __nv_bfloat16 *xh, *xl, *wh, *wl, *qh, *ql, *kh, *kl, *vh, *vl, *oh, *ol;
    cudaGetSymbolAddress((void**)&xh, g_xhi);
    cudaGetSymbolAddress((void**)&xl, g_xlo);
    cudaGetSymbolAddress((void**)&wh, g_whi);
    cudaGetSymbolAddress((void**)&wl, g_wlo);
    cudaGetSymbolAddress((void**)&qh, g_qhi);
    cudaGetSymbolAddress((void**)&ql, g_qlo);
    cudaGetSymbolAddress((void**)&kh, g_khi);
    cudaGetSymbolAddress((void**)&kl, g_klo);
    cudaGetSymbolAddress((void**)&vh, g_vhi);
    cudaGetSymbolAddress((void**)&vl, g_vlo);
    cudaGetSymbolAddress((void**)&oh, g_ohi);
    cudaGetSymbolAddress((void**)&ol, g_olo);

    cudaFuncSetAttribute(flash_mma,
                         cudaFuncAttributeMaxDynamicSharedMemorySize, FSM_BYTES);
    cudaFuncSetAttribute(gemm_qkv,
                         cudaFuncAttributeMaxDynamicSharedMemorySize, GSM_BYTES);
    cudaFuncSetAttribute(gemm_pre,
                         cudaFuncAttributeMaxDynamicSharedMemorySize, GSM_BYTES);

    const int NX = Mrows*Cc;
    const int NW = Cc*Cc;

    split_f32<<<NX/4/256, 256>>>(x, xh, xl, NX);
    split_w4<<<dim3(NW/4/256, 4), 256>>>(Wq, Wk, Wv, Wo, wh, wl);

    gemm_qkv<<<dim3(Cc/128, Mrows/128, 3), 256, GSM_BYTES>>>(
        xh, xl, wh, wl, Qp, Kp, vh, vl);

    rope_rms_split<<<Mrows, 384>>>(Qp, Kp, cs, sn, qh, ql, kh, kl);

    flash_mma<<<dim3(Bc*Hc, Tc/128), 256, FSM_BYTES>>>(qh, ql, kh, kl, vh, vl, oh, ol);

    gemm_pre<<<dim3(Cc/128, Mrows/128), 256, GSM_BYTES>>>(
        oh, ol, wh + 3*NW, wl + 3*NW, out, Mrows, Cc, Cc);
}